// round 5
// baseline (speedup 1.0000x reference)
#include <cuda_runtime.h>
#include <math.h>

#define NN 50000
#define EE 800000
#define ET (EE + NN)   // edges + self loops = 850000

// ---------------- scratch (device globals; no allocations allowed) ----------------
__device__ float g_h1[NN * 256];     // x @ W1
__device__ float g_hga[NN * 256];    // GAT1 output (+b1)
__device__ float g_hn[NN * 256];     // BN1 + ELU
__device__ float g_hp[NN * 64];      // hn @ Wg
__device__ float g_hgcn[NN * 64];    // GCN out (+bg)
__device__ float g_hr[NN * 64];      // BN2 + ReLU
__device__ float g_h3[NN * 64];      // hr @ W2
__device__ float g_hga2[NN * 64];    // GAT2 out (+b2)
__device__ float g_z[NN * 64];       // BN3 + ELU
__device__ float g_p1[NN * 128];     // relu(z@Wp1+bp1)

__device__ float g_es1[NN * 4], g_ed1[NN * 4], g_emax1[NN * 4];
__device__ float g_es2[NN], g_ed2[NN], g_emax2[NN], g_dinv[NN];
__device__ int   g_deg[NN];
__device__ int   g_rowptr[NN + 1];
__device__ int   g_cursor[NN];
__device__ int   g_srcs[ET];
__device__ float g_bnstats[512];           // [0..255]=sum, [256..511]=sumsq
__device__ float g_scale[256], g_shift[256];

// ---------------- helpers ----------------
__device__ __forceinline__ void atomicMaxF(float* addr, float v) {
    int* a = (int*)addr;
    int old = *a;
    while (__int_as_float(old) < v) {
        int assumed = old;
        old = atomicCAS(a, assumed, __float_as_int(v));
        if (old == assumed) break;
    }
}

// ---------------- init ----------------
__global__ void init_k() {
    int i = blockIdx.x * blockDim.x + threadIdx.x;
    if (i < NN * 4) g_emax1[i] = -1e30f;
    if (i < NN) { g_deg[i] = 0; g_emax2[i] = -1e30f; }
}

__global__ void zstats_k() {
    int i = threadIdx.x;
    if (i < 512) g_bnstats[i] = 0.0f;
}

// ---------------- SGEMM: C[M,Nc] = A[M,K] @ B[K,Nc] (+bias, act) ----------------
// 64x64 block tile, 16 k-tile, 256 threads, 4x4 microtile. act: 0 none, 1 relu.
__global__ void sgemm(const float* __restrict__ A, const float* __restrict__ B,
                      float* __restrict__ C, int M, int K, int Nc,
                      const float* __restrict__ bias, int act)
{
    __shared__ float As[16][68];
    __shared__ float Bs[16][68];
    int tid = threadIdx.x;
    int tx = tid & 15, ty = tid >> 4;
    int m0 = blockIdx.x * 64, n0 = blockIdx.y * 64;

    float acc[4][4] = {};

    int ar = tid >> 2;            // 0..63 (A tile row)
    int aq = (tid & 3) * 4;       // A tile col base
    int bk = tid >> 4;            // 0..15 (B tile row)
    int bq = (tid & 15) * 4;      // B tile col base

    for (int k0 = 0; k0 < K; k0 += 16) {
        int arow = m0 + ar;
        float4 av = make_float4(0.f, 0.f, 0.f, 0.f);
        if (arow < M) av = *(const float4*)(A + (size_t)arow * K + k0 + aq);
        As[aq + 0][ar] = av.x; As[aq + 1][ar] = av.y;
        As[aq + 2][ar] = av.z; As[aq + 3][ar] = av.w;

        float4 bv = *(const float4*)(B + (size_t)(k0 + bk) * Nc + n0 + bq);
        *(float4*)&Bs[bk][bq] = bv;
        __syncthreads();

        #pragma unroll
        for (int kk = 0; kk < 16; kk++) {
            float4 a = *(float4*)&As[kk][ty * 4];
            float4 b = *(float4*)&Bs[kk][tx * 4];
            float ra[4] = {a.x, a.y, a.z, a.w};
            float rb[4] = {b.x, b.y, b.z, b.w};
            #pragma unroll
            for (int i = 0; i < 4; i++)
                #pragma unroll
                for (int j = 0; j < 4; j++)
                    acc[i][j] = fmaf(ra[i], rb[j], acc[i][j]);
        }
        __syncthreads();
    }

    float4 bb = make_float4(0.f, 0.f, 0.f, 0.f);
    if (bias) bb = *(const float4*)(bias + n0 + tx * 4);
    #pragma unroll
    for (int i = 0; i < 4; i++) {
        int m = m0 + ty * 4 + i;
        if (m < M) {
            float4 v;
            v.x = acc[i][0] + bb.x; v.y = acc[i][1] + bb.y;
            v.z = acc[i][2] + bb.z; v.w = acc[i][3] + bb.w;
            if (act == 1) {
                v.x = fmaxf(v.x, 0.f); v.y = fmaxf(v.y, 0.f);
                v.z = fmaxf(v.z, 0.f); v.w = fmaxf(v.w, 0.f);
            }
            *(float4*)(C + (size_t)m * Nc + n0 + tx * 4) = v;
        }
    }
}

// ---------------- attention dot products, layer 1 (warp per node) ----------------
__global__ void dots1_k(const float* __restrict__ asrc, const float* __restrict__ adst) {
    int warp = (blockIdx.x * blockDim.x + threadIdx.x) >> 5;
    int lane = threadIdx.x & 31;
    if (warp >= NN) return;
    const float* row = g_h1 + (size_t)warp * 256;
    float ps[4] = {0, 0, 0, 0}, pd[4] = {0, 0, 0, 0};
    #pragma unroll
    for (int k = 0; k < 8; k++) {
        int f = lane + 32 * k;
        float v = row[f];
        ps[k >> 1] += v * asrc[f];
        pd[k >> 1] += v * adst[f];
    }
    #pragma unroll
    for (int o = 16; o; o >>= 1) {
        #pragma unroll
        for (int h = 0; h < 4; h++) {
            ps[h] += __shfl_xor_sync(0xffffffffu, ps[h], o);
            pd[h] += __shfl_xor_sync(0xffffffffu, pd[h], o);
        }
    }
    if (lane == 0) {
        #pragma unroll
        for (int h = 0; h < 4; h++) {
            g_es1[warp * 4 + h] = ps[h];
            g_ed1[warp * 4 + h] = pd[h];
        }
    }
}

// ---------------- CSR build ----------------
__global__ void hist_k(const int* __restrict__ ei) {
    int i = blockIdx.x * blockDim.x + threadIdx.x;
    if (i >= ET) return;
    int dst = (i < EE) ? ei[EE + i] : (i - EE);
    atomicAdd(&g_deg[dst], 1);
}

__global__ void scan_k() {
    __shared__ int sm[1024];
    int tid = threadIdx.x;
    const int CH = (NN + 1023) / 1024;
    int start = tid * CH;
    int end = min(start + CH, NN);
    int s = 0;
    for (int i = start; i < end; i++) s += g_deg[i];
    sm[tid] = s;
    __syncthreads();
    for (int off = 1; off < 1024; off <<= 1) {
        int v = (tid >= off) ? sm[tid - off] : 0;
        __syncthreads();
        sm[tid] += v;
        __syncthreads();
    }
    int run = (tid == 0) ? 0 : sm[tid - 1];
    for (int i = start; i < end; i++) {
        g_rowptr[i] = run;
        g_cursor[i] = run;
        run += g_deg[i];
    }
    if (tid == 1023) g_rowptr[NN] = sm[1023];
}

__global__ void scatter_k(const int* __restrict__ ei) {
    int i = blockIdx.x * blockDim.x + threadIdx.x;
    if (i >= ET) return;
    int src = (i < EE) ? ei[i] : (i - EE);
    int dst = (i < EE) ? ei[EE + i] : (i - EE);
    int pos = atomicAdd(&g_cursor[dst], 1);
    g_srcs[pos] = src;
}

// ---------------- edge max (softmax pass 1) ----------------
__global__ void emax1_k(const int* __restrict__ ei) {
    int i = blockIdx.x * blockDim.x + threadIdx.x;
    if (i >= ET) return;
    int src = (i < EE) ? ei[i] : (i - EE);
    int dst = (i < EE) ? ei[EE + i] : (i - EE);
    float4 es = *(const float4*)(g_es1 + src * 4);
    float4 ed = *(const float4*)(g_ed1 + dst * 4);
    float e;
    e = es.x + ed.x; e = fmaxf(e, 0.2f * e); atomicMaxF(&g_emax1[dst * 4 + 0], e);
    e = es.y + ed.y; e = fmaxf(e, 0.2f * e); atomicMaxF(&g_emax1[dst * 4 + 1], e);
    e = es.z + ed.z; e = fmaxf(e, 0.2f * e); atomicMaxF(&g_emax1[dst * 4 + 2], e);
    e = es.w + ed.w; e = fmaxf(e, 0.2f * e); atomicMaxF(&g_emax1[dst * 4 + 3], e);
}

__global__ void emax2_k(const int* __restrict__ ei) {
    int i = blockIdx.x * blockDim.x + threadIdx.x;
    if (i >= ET) return;
    int src = (i < EE) ? ei[i] : (i - EE);
    int dst = (i < EE) ? ei[EE + i] : (i - EE);
    float e = g_es2[src] + g_ed2[dst];
    e = fmaxf(e, 0.2f * e);
    atomicMaxF(&g_emax2[dst], e);
}

// ---------------- GAT1 aggregation (warp per node, fused softmax pass 2) ----------------
__global__ void gat1_agg_k(const float* __restrict__ b1) {
    int warp = (blockIdx.x * blockDim.x + threadIdx.x) >> 5;
    int lane = threadIdx.x & 31;
    if (warp >= NN) return;
    int n = warp;
    float4 edv = *(const float4*)(g_ed1 + n * 4);
    float4 emx = *(const float4*)(g_emax1 + n * 4);
    float acc[8] = {0, 0, 0, 0, 0, 0, 0, 0};
    float den[4] = {0, 0, 0, 0};
    int jb = g_rowptr[n], je = g_rowptr[n + 1];
    for (int j = jb; j < je; j++) {
        int s = g_srcs[j];
        float4 esv = *(const float4*)(g_es1 + s * 4);
        float w[4];
        float e;
        e = esv.x + edv.x; e = fmaxf(e, 0.2f * e); w[0] = __expf(e - emx.x); den[0] += w[0];
        e = esv.y + edv.y; e = fmaxf(e, 0.2f * e); w[1] = __expf(e - emx.y); den[1] += w[1];
        e = esv.z + edv.z; e = fmaxf(e, 0.2f * e); w[2] = __expf(e - emx.z); den[2] += w[2];
        e = esv.w + edv.w; e = fmaxf(e, 0.2f * e); w[3] = __expf(e - emx.w); den[3] += w[3];
        const float* row = g_h1 + (size_t)s * 256;
        #pragma unroll
        for (int k = 0; k < 8; k++)
            acc[k] = fmaf(w[k >> 1], row[lane + 32 * k], acc[k]);
    }
    #pragma unroll
    for (int k = 0; k < 8; k++) {
        int f = lane + 32 * k;
        g_hga[(size_t)n * 256 + f] = acc[k] / (den[k >> 1] + 1e-16f) + b1[f];
    }
}

// ---------------- BN: stats / params / apply ----------------
__global__ void bn_stats_k(const float* __restrict__ X, int C) {
    int tid = threadIdx.x;                 // 256 threads
    int c = tid & (C - 1);
    int rlocal = tid / C;
    int rstride = 256 / C;
    int r0 = blockIdx.x * 256;
    int rend = min(r0 + 256, NN);
    float s = 0.f, q = 0.f;
    for (int r = r0 + rlocal; r < rend; r += rstride) {
        float v = X[(size_t)r * C + c];
        s += v; q += v * v;
    }
    atomicAdd(&g_bnstats[c], s);
    atomicAdd(&g_bnstats[256 + c], q);
}

__global__ void bn_params_k(const float* __restrict__ g, const float* __restrict__ beta, int C) {
    int c = threadIdx.x;
    if (c < C) {
        float mu = g_bnstats[c] / (float)NN;
        float var = g_bnstats[256 + c] / (float)NN - mu * mu;
        float sc = rsqrtf(var + 1e-5f) * g[c];
        g_scale[c] = sc;
        g_shift[c] = beta[c] - mu * sc;
    }
}

// act: 1 = relu, 2 = elu
__global__ void bn_apply_k(const float* __restrict__ X, float* __restrict__ Y, int C, int act) {
    int i = blockIdx.x * blockDim.x + threadIdx.x;
    if (i >= NN * C) return;
    int c = i & (C - 1);
    float v = X[i] * g_scale[c] + g_shift[c];
    if (act == 1) v = fmaxf(v, 0.f);
    else v = (v > 0.f) ? v : expm1f(v);
    Y[i] = v;
}

// ---------------- GCN ----------------
__global__ void dinv_k() {
    int i = blockIdx.x * blockDim.x + threadIdx.x;
    if (i >= NN) return;
    float d = (float)(g_rowptr[i + 1] - g_rowptr[i]);
    g_dinv[i] = rsqrtf(fmaxf(d, 1e-12f));
}

__global__ void gcn_agg_k(const float* __restrict__ bg) {
    int warp = (blockIdx.x * blockDim.x + threadIdx.x) >> 5;
    int lane = threadIdx.x & 31;
    if (warp >= NN) return;
    int n = warp;
    float dn = g_dinv[n];
    float a0 = 0.f, a1 = 0.f;
    int jb = g_rowptr[n], je = g_rowptr[n + 1];
    for (int j = jb; j < je; j++) {
        int s = g_srcs[j];
        float w = g_dinv[s] * dn;
        const float* row = g_hp + (size_t)s * 64;
        a0 = fmaf(w, row[lane], a0);
        a1 = fmaf(w, row[lane + 32], a1);
    }
    g_hgcn[(size_t)n * 64 + lane]      = a0 + bg[lane];
    g_hgcn[(size_t)n * 64 + lane + 32] = a1 + bg[lane + 32];
}

// ---------------- GAT2 (single head) ----------------
__global__ void dots2_k(const float* __restrict__ asrc, const float* __restrict__ adst) {
    int warp = (blockIdx.x * blockDim.x + threadIdx.x) >> 5;
    int lane = threadIdx.x & 31;
    if (warp >= NN) return;
    const float* row = g_h3 + (size_t)warp * 64;
    float v0 = row[lane], v1 = row[lane + 32];
    float ps = v0 * asrc[lane] + v1 * asrc[lane + 32];
    float pd = v0 * adst[lane] + v1 * adst[lane + 32];
    #pragma unroll
    for (int o = 16; o; o >>= 1) {
        ps += __shfl_xor_sync(0xffffffffu, ps, o);
        pd += __shfl_xor_sync(0xffffffffu, pd, o);
    }
    if (lane == 0) { g_es2[warp] = ps; g_ed2[warp] = pd; }
}

__global__ void gat2_agg_k(const float* __restrict__ b2) {
    int warp = (blockIdx.x * blockDim.x + threadIdx.x) >> 5;
    int lane = threadIdx.x & 31;
    if (warp >= NN) return;
    int n = warp;
    float edv = g_ed2[n];
    float emx = g_emax2[n];
    float den = 0.f, a0 = 0.f, a1 = 0.f;
    int jb = g_rowptr[n], je = g_rowptr[n + 1];
    for (int j = jb; j < je; j++) {
        int s = g_srcs[j];
        float e = g_es2[s] + edv;
        e = fmaxf(e, 0.2f * e);
        float w = __expf(e - emx);
        den += w;
        const float* row = g_h3 + (size_t)s * 64;
        a0 = fmaf(w, row[lane], a0);
        a1 = fmaf(w, row[lane + 32], a1);
    }
    float inv = 1.f / (den + 1e-16f);
    g_hga2[(size_t)n * 64 + lane]      = a0 * inv + b2[lane];
    g_hga2[(size_t)n * 64 + lane + 32] = a1 * inv + b2[lane + 32];
}

// ---------------- host ----------------
static float* symf(const void* sym) {
    void* p = nullptr;
    cudaGetSymbolAddress(&p, sym);
    return (float*)p;
}

extern "C" void kernel_launch(void* const* d_in, const int* in_sizes, int n_in,
                              void* d_out, int out_size) {
    const float* x   = (const float*)d_in[0];
    const int*   ei  = (const int*)d_in[1];
    // d_in[2] = edge_attr (ignored by reference)
    const float* W1  = (const float*)d_in[3];
    const float* as1 = (const float*)d_in[4];
    const float* ad1 = (const float*)d_in[5];
    const float* b1  = (const float*)d_in[6];
    const float* g1  = (const float*)d_in[7];
    const float* be1 = (const float*)d_in[8];
    const float* Wg  = (const float*)d_in[9];
    const float* bg  = (const float*)d_in[10];
    const float* g2  = (const float*)d_in[11];
    const float* be2 = (const float*)d_in[12];
    const float* W2  = (const float*)d_in[13];
    const float* as2 = (const float*)d_in[14];
    const float* ad2 = (const float*)d_in[15];
    const float* b2  = (const float*)d_in[16];
    const float* g3  = (const float*)d_in[17];
    const float* be3 = (const float*)d_in[18];
    const float* Wp1 = (const float*)d_in[19];
    const float* bp1 = (const float*)d_in[20];
    const float* Wp2 = (const float*)d_in[21];
    const float* bp2 = (const float*)d_in[22];
    float* out = (float*)d_out;

    float* p_h1   = symf(g_h1);
    float* p_hga  = symf(g_hga);
    float* p_hn   = symf(g_hn);
    float* p_hp   = symf(g_hp);
    float* p_hgcn = symf(g_hgcn);
    float* p_hr   = symf(g_hr);
    float* p_h3   = symf(g_h3);
    float* p_hga2 = symf(g_hga2);
    float* p_z    = symf(g_z);
    float* p_p1   = symf(g_p1);

    const int EB = (ET + 255) / 256;            // edge-parallel grid
    const int WB = (NN + 7) / 8;                // warp-per-node grid (8 warps/block)
    const int GX = (NN + 63) / 64;              // sgemm row blocks

    // init scratch
    init_k<<<(NN * 4 + 255) / 256, 256>>>();

    // h1 = x @ W1
    sgemm<<<dim3(GX, 4), 256>>>(x, W1, p_h1, NN, 128, 256, nullptr, 0);
    dots1_k<<<WB, 256>>>(as1, ad1);

    // CSR by dst (with self loops)
    hist_k<<<EB, 256>>>(ei);
    scan_k<<<1, 1024>>>();
    scatter_k<<<EB, 256>>>(ei);

    // GAT layer 1
    emax1_k<<<EB, 256>>>(ei);
    gat1_agg_k<<<WB, 256>>>(b1);

    // BN1 + ELU
    zstats_k<<<1, 512>>>();
    bn_stats_k<<<(NN + 255) / 256, 256>>>(p_hga, 256);
    bn_params_k<<<1, 256>>>(g1, be1, 256);
    bn_apply_k<<<(NN * 256 + 255) / 256, 256>>>(p_hga, p_hn, 256, 2);

    // GCN
    sgemm<<<dim3(GX, 1), 256>>>(p_hn, Wg, p_hp, NN, 256, 64, nullptr, 0);
    dinv_k<<<(NN + 255) / 256, 256>>>();
    gcn_agg_k<<<WB, 256>>>(bg);

    // BN2 + ReLU
    zstats_k<<<1, 512>>>();
    bn_stats_k<<<(NN + 255) / 256, 256>>>(p_hgcn, 64);
    bn_params_k<<<1, 256>>>(g2, be2, 64);
    bn_apply_k<<<(NN * 64 + 255) / 256, 256>>>(p_hgcn, p_hr, 64, 1);

    // GAT layer 2
    sgemm<<<dim3(GX, 1), 256>>>(p_hr, W2, p_h3, NN, 64, 64, nullptr, 0);
    dots2_k<<<WB, 256>>>(as2, ad2);
    emax2_k<<<EB, 256>>>(ei);
    gat2_agg_k<<<WB, 256>>>(b2);

    // BN3 + ELU
    zstats_k<<<1, 512>>>();
    bn_stats_k<<<(NN + 255) / 256, 256>>>(p_hga2, 64);
    bn_params_k<<<1, 256>>>(g3, be3, 64);
    bn_apply_k<<<(NN * 64 + 255) / 256, 256>>>(p_hga2, p_z, 64, 2);

    // projector
    sgemm<<<dim3(GX, 2), 256>>>(p_z, Wp1, p_p1, NN, 64, 128, bp1, 1);
    sgemm<<<dim3(GX, 1), 256>>>(p_p1, Wp2, out, NN, 128, 64, bp2, 0);
}

// round 6
// speedup vs baseline: 1.2155x; 1.2155x over previous
#include <cuda_runtime.h>
#include <math.h>

#define NN 50000
#define EE 800000
#define ET (EE + NN)   // edges + self loops = 850000

typedef unsigned long long ull;

// ---------------- scratch (device globals; no allocations allowed) ----------------
__device__ float g_h1[NN * 256];     // x @ W1
__device__ float g_hga[NN * 256];    // GAT1 output (+b1), pre-BN
__device__ float g_hp[NN * 64];      // BN1+ELU(hga) @ Wg
__device__ float g_hgcn[NN * 64];    // GCN out (+bg), pre-BN
__device__ float g_h3[NN * 64];      // BN2+ReLU(hgcn) @ W2
__device__ float g_hga2[NN * 64];    // GAT2 out (+b2), pre-BN
__device__ float g_p1[NN * 128];     // relu(BN3+ELU(hga2) @ Wp1 + bp1)

__device__ float g_es1[NN * 4], g_ed1[NN * 4];
__device__ float g_es2[NN], g_ed2[NN], g_dinv[NN];
__device__ int   g_deg[NN];
__device__ int   g_rowptr[NN + 1];
__device__ int   g_cursor[NN];
__device__ int   g_srcs[ET];
__device__ float g_bnstats[512];           // [0..255]=sum, [256..511]=sumsq
__device__ float g_scale[256], g_shift[256];

// ---------------- f32x2 packed math ----------------
__device__ __forceinline__ ull pack2(float v) {
    ull p; unsigned r = __float_as_uint(v);
    asm("mov.b64 %0, {%1, %2};" : "=l"(p) : "r"(r), "r"(r));
    return p;
}
__device__ __forceinline__ ull fma2(ull a, ull b, ull c) {
    ull d;
    asm("fma.rn.f32x2 %0, %1, %2, %3;" : "=l"(d) : "l"(a), "l"(b), "l"(c));
    return d;
}
__device__ __forceinline__ void unpack2(ull p, float& lo, float& hi) {
    unsigned a, b;
    asm("mov.b64 {%0, %1}, %2;" : "=r"(a), "=r"(b) : "l"(p));
    lo = __uint_as_float(a); hi = __uint_as_float(b);
}

// ---------------- init ----------------
__global__ void zdeg_k() {
    int i = blockIdx.x * blockDim.x + threadIdx.x;
    if (i < NN) g_deg[i] = 0;
}
__global__ void zstats_k() {
    int i = threadIdx.x;
    if (i < 512) g_bnstats[i] = 0.0f;
}

// ---------------- SGEMM v2: C[M,Nc] = T(A)[M,K] @ B[K,Nc] (+bias, act) ----------------
// 128x64 block tile, KT=16, 256 threads, 8x4 microtile with M-pairwise f32x2 accumulators.
// T(A): optional per-column scale/shift (BN) + activation (aact: 0 none, 1 relu, 2 elu).
// Epilogue act: 0 none, 1 relu.
__device__ __forceinline__ float atransform(float v, int col, const float* sc,
                                            const float* sh, int aact) {
    if (sc) v = fmaf(v, __ldg(sc + col), __ldg(sh + col));
    if (aact == 1) v = fmaxf(v, 0.f);
    else if (aact == 2) v = (v > 0.f) ? v : (__expf(v) - 1.0f);
    return v;
}

__global__ void sgemm2(const float* __restrict__ A, const float* __restrict__ B,
                       float* __restrict__ C, int M, int K, int Nc,
                       const float* __restrict__ bias, int act,
                       const float* __restrict__ ascale, const float* __restrict__ ashift,
                       int aact)
{
    __shared__ float As[16][130];   // k-major; stride 130 -> conflict-free scalar stores
    __shared__ float Bs[16][64];

    const int tid = threadIdx.x;
    const int tx = tid & 15, ty = tid >> 4;
    const int m0 = blockIdx.x * 128, n0 = blockIdx.y * 64;

    const int ar = tid >> 1;            // 0..127 A tile row
    const int ac = (tid & 1) * 8;       // A tile col base (two float4)
    const int br = tid >> 4;            // 0..15 B tile row
    const int bc = (tid & 15) * 4;      // B tile col base
    const int arow = m0 + ar;
    const bool avalid = arow < M;

    ull acc[4][4];
    #pragma unroll
    for (int i = 0; i < 4; i++)
        #pragma unroll
        for (int j = 0; j < 4; j++) acc[i][j] = 0ull;

    for (int k0 = 0; k0 < K; k0 += 16) {
        float4 av0 = make_float4(0.f, 0.f, 0.f, 0.f);
        float4 av1 = make_float4(0.f, 0.f, 0.f, 0.f);
        if (avalid) {
            const float* ap = A + (size_t)arow * K + k0 + ac;
            av0 = *(const float4*)ap;
            av1 = *(const float4*)(ap + 4);
            if (aact) {
                int c = k0 + ac;
                av0.x = atransform(av0.x, c + 0, ascale, ashift, aact);
                av0.y = atransform(av0.y, c + 1, ascale, ashift, aact);
                av0.z = atransform(av0.z, c + 2, ascale, ashift, aact);
                av0.w = atransform(av0.w, c + 3, ascale, ashift, aact);
                av1.x = atransform(av1.x, c + 4, ascale, ashift, aact);
                av1.y = atransform(av1.y, c + 5, ascale, ashift, aact);
                av1.z = atransform(av1.z, c + 6, ascale, ashift, aact);
                av1.w = atransform(av1.w, c + 7, ascale, ashift, aact);
            }
        }
        As[ac + 0][ar] = av0.x; As[ac + 1][ar] = av0.y;
        As[ac + 2][ar] = av0.z; As[ac + 3][ar] = av0.w;
        As[ac + 4][ar] = av1.x; As[ac + 5][ar] = av1.y;
        As[ac + 6][ar] = av1.z; As[ac + 7][ar] = av1.w;

        *(float4*)&Bs[br][bc] = *(const float4*)(B + (size_t)(k0 + br) * Nc + n0 + bc);
        __syncthreads();

        #pragma unroll
        for (int kk = 0; kk < 16; kk++) {
            const float* ap = &As[kk][ty * 8];
            ull a0 = *(const ull*)(ap + 0);
            ull a1 = *(const ull*)(ap + 2);
            ull a2 = *(const ull*)(ap + 4);
            ull a3 = *(const ull*)(ap + 6);
            float4 bv = *(const float4*)&Bs[kk][tx * 4];
            ull b0 = pack2(bv.x), b1 = pack2(bv.y), b2 = pack2(bv.z), b3 = pack2(bv.w);
            acc[0][0] = fma2(a0, b0, acc[0][0]);
            acc[0][1] = fma2(a0, b1, acc[0][1]);
            acc[0][2] = fma2(a0, b2, acc[0][2]);
            acc[0][3] = fma2(a0, b3, acc[0][3]);
            acc[1][0] = fma2(a1, b0, acc[1][0]);
            acc[1][1] = fma2(a1, b1, acc[1][1]);
            acc[1][2] = fma2(a1, b2, acc[1][2]);
            acc[1][3] = fma2(a1, b3, acc[1][3]);
            acc[2][0] = fma2(a2, b0, acc[2][0]);
            acc[2][1] = fma2(a2, b1, acc[2][1]);
            acc[2][2] = fma2(a2, b2, acc[2][2]);
            acc[2][3] = fma2(a2, b3, acc[2][3]);
            acc[3][0] = fma2(a3, b0, acc[3][0]);
            acc[3][1] = fma2(a3, b1, acc[3][1]);
            acc[3][2] = fma2(a3, b2, acc[3][2]);
            acc[3][3] = fma2(a3, b3, acc[3][3]);
        }
        __syncthreads();
    }

    float4 bb = make_float4(0.f, 0.f, 0.f, 0.f);
    if (bias) bb = *(const float4*)(bias + n0 + tx * 4);

    #pragma unroll
    for (int i = 0; i < 4; i++) {
        float lo0, hi0, lo1, hi1, lo2, hi2, lo3, hi3;
        unpack2(acc[i][0], lo0, hi0);
        unpack2(acc[i][1], lo1, hi1);
        unpack2(acc[i][2], lo2, hi2);
        unpack2(acc[i][3], lo3, hi3);
        int r0 = m0 + ty * 8 + 2 * i;
        if (r0 < M) {
            float4 v;
            v.x = lo0 + bb.x; v.y = lo1 + bb.y; v.z = lo2 + bb.z; v.w = lo3 + bb.w;
            if (act == 1) {
                v.x = fmaxf(v.x, 0.f); v.y = fmaxf(v.y, 0.f);
                v.z = fmaxf(v.z, 0.f); v.w = fmaxf(v.w, 0.f);
            }
            *(float4*)(C + (size_t)r0 * Nc + n0 + tx * 4) = v;
        }
        if (r0 + 1 < M) {
            float4 v;
            v.x = hi0 + bb.x; v.y = hi1 + bb.y; v.z = hi2 + bb.z; v.w = hi3 + bb.w;
            if (act == 1) {
                v.x = fmaxf(v.x, 0.f); v.y = fmaxf(v.y, 0.f);
                v.z = fmaxf(v.z, 0.f); v.w = fmaxf(v.w, 0.f);
            }
            *(float4*)(C + (size_t)(r0 + 1) * Nc + n0 + tx * 4) = v;
        }
    }
}

// ---------------- attention dot products, layer 1 (warp per node) ----------------
__global__ void dots1_k(const float* __restrict__ asrc, const float* __restrict__ adst) {
    int warp = (blockIdx.x * blockDim.x + threadIdx.x) >> 5;
    int lane = threadIdx.x & 31;
    if (warp >= NN) return;
    const float* row = g_h1 + (size_t)warp * 256;
    float ps[4] = {0, 0, 0, 0}, pd[4] = {0, 0, 0, 0};
    #pragma unroll
    for (int k = 0; k < 8; k++) {
        int f = lane + 32 * k;
        float v = row[f];
        ps[k >> 1] += v * asrc[f];
        pd[k >> 1] += v * adst[f];
    }
    #pragma unroll
    for (int o = 16; o; o >>= 1) {
        #pragma unroll
        for (int h = 0; h < 4; h++) {
            ps[h] += __shfl_xor_sync(0xffffffffu, ps[h], o);
            pd[h] += __shfl_xor_sync(0xffffffffu, pd[h], o);
        }
    }
    if (lane == 0) {
        #pragma unroll
        for (int h = 0; h < 4; h++) {
            g_es1[warp * 4 + h] = ps[h];
            g_ed1[warp * 4 + h] = pd[h];
        }
    }
}

// ---------------- CSR build ----------------
__global__ void hist_k(const int* __restrict__ ei) {
    int i = blockIdx.x * blockDim.x + threadIdx.x;
    if (i >= ET) return;
    int dst = (i < EE) ? ei[EE + i] : (i - EE);
    atomicAdd(&g_deg[dst], 1);
}

__global__ void scan_k() {
    __shared__ int sm[1024];
    int tid = threadIdx.x;
    const int CH = (NN + 1023) / 1024;
    int start = tid * CH;
    int end = min(start + CH, NN);
    int s = 0;
    for (int i = start; i < end; i++) s += g_deg[i];
    sm[tid] = s;
    __syncthreads();
    for (int off = 1; off < 1024; off <<= 1) {
        int v = (tid >= off) ? sm[tid - off] : 0;
        __syncthreads();
        sm[tid] += v;
        __syncthreads();
    }
    int run = (tid == 0) ? 0 : sm[tid - 1];
    for (int i = start; i < end; i++) {
        g_rowptr[i] = run;
        g_cursor[i] = run;
        run += g_deg[i];
    }
    if (tid == 1023) g_rowptr[NN] = sm[1023];
}

__global__ void scatter_k(const int* __restrict__ ei) {
    int i = blockIdx.x * blockDim.x + threadIdx.x;
    if (i >= ET) return;
    int src = (i < EE) ? ei[i] : (i - EE);
    int dst = (i < EE) ? ei[EE + i] : (i - EE);
    int pos = atomicAdd(&g_cursor[dst], 1);
    g_srcs[pos] = src;
}

// ---------------- GAT1 aggregation: in-warp max + fused softmax + gather ----------------
__global__ void gat1_agg_k(const float* __restrict__ b1) {
    int warp = (blockIdx.x * blockDim.x + threadIdx.x) >> 5;
    int lane = threadIdx.x & 31;
    if (warp >= NN) return;
    int n = warp;
    int jb = g_rowptr[n], je = g_rowptr[n + 1];
    float4 edv = *(const float4*)(g_ed1 + n * 4);

    // pass 1: per-head max, lane-parallel over neighbors
    float m0 = -1e30f, m1 = -1e30f, m2 = -1e30f, m3 = -1e30f;
    for (int j = jb + lane; j < je; j += 32) {
        int s = __ldg(g_srcs + j);
        float4 es = *(const float4*)(g_es1 + s * 4);
        float e;
        e = es.x + edv.x; e = fmaxf(e, 0.2f * e); m0 = fmaxf(m0, e);
        e = es.y + edv.y; e = fmaxf(e, 0.2f * e); m1 = fmaxf(m1, e);
        e = es.z + edv.z; e = fmaxf(e, 0.2f * e); m2 = fmaxf(m2, e);
        e = es.w + edv.w; e = fmaxf(e, 0.2f * e); m3 = fmaxf(m3, e);
    }
    #pragma unroll
    for (int o = 16; o; o >>= 1) {
        m0 = fmaxf(m0, __shfl_xor_sync(0xffffffffu, m0, o));
        m1 = fmaxf(m1, __shfl_xor_sync(0xffffffffu, m1, o));
        m2 = fmaxf(m2, __shfl_xor_sync(0xffffffffu, m2, o));
        m3 = fmaxf(m3, __shfl_xor_sync(0xffffffffu, m3, o));
    }

    // pass 2: weights + vectorized gather. lane covers features [lane*4..+3] and [128+lane*4..+3]
    int h0 = lane >> 4;   // head of first float4 (0 or 1); second is h0+2
    float4 acc0 = make_float4(0.f, 0.f, 0.f, 0.f);
    float4 acc1 = make_float4(0.f, 0.f, 0.f, 0.f);
    float den0 = 0.f, den1 = 0.f, den2 = 0.f, den3 = 0.f;
    const float4* base = (const float4*)g_h1;
    for (int j = jb; j < je; j++) {
        int s = __ldg(g_srcs + j);
        float4 es = *(const float4*)(g_es1 + s * 4);
        float e, w0, w1, w2, w3;
        e = es.x + edv.x; e = fmaxf(e, 0.2f * e); w0 = __expf(e - m0); den0 += w0;
        e = es.y + edv.y; e = fmaxf(e, 0.2f * e); w1 = __expf(e - m1); den1 += w1;
        e = es.z + edv.z; e = fmaxf(e, 0.2f * e); w2 = __expf(e - m2); den2 += w2;
        e = es.w + edv.w; e = fmaxf(e, 0.2f * e); w3 = __expf(e - m3); den3 += w3;
        float wa = h0 ? w1 : w0;
        float wb = h0 ? w3 : w2;
        const float4* row = base + (size_t)s * 64;
        float4 a = row[lane];
        float4 b = row[lane + 32];
        acc0.x = fmaf(wa, a.x, acc0.x); acc0.y = fmaf(wa, a.y, acc0.y);
        acc0.z = fmaf(wa, a.z, acc0.z); acc0.w = fmaf(wa, a.w, acc0.w);
        acc1.x = fmaf(wb, b.x, acc1.x); acc1.y = fmaf(wb, b.y, acc1.y);
        acc1.z = fmaf(wb, b.z, acc1.z); acc1.w = fmaf(wb, b.w, acc1.w);
    }
    float ia = 1.f / ((h0 ? den1 : den0) + 1e-16f);
    float ib = 1.f / ((h0 ? den3 : den2) + 1e-16f);
    int f = lane * 4;
    float4 ba = *(const float4*)(b1 + f);
    float4 bb = *(const float4*)(b1 + 128 + f);
    float4 oa, ob;
    oa.x = acc0.x * ia + ba.x; oa.y = acc0.y * ia + ba.y;
    oa.z = acc0.z * ia + ba.z; oa.w = acc0.w * ia + ba.w;
    ob.x = acc1.x * ib + bb.x; ob.y = acc1.y * ib + bb.y;
    ob.z = acc1.z * ib + bb.z; ob.w = acc1.w * ib + bb.w;
    *(float4*)(g_hga + (size_t)n * 256 + f) = oa;
    *(float4*)(g_hga + (size_t)n * 256 + 128 + f) = ob;
}

// ---------------- BN stats / params ----------------
__global__ void bn_stats_k(const float* __restrict__ X, int C) {
    int tid = threadIdx.x;                 // 256 threads
    int c = tid & (C - 1);
    int rlocal = tid / C;
    int rstride = 256 / C;
    int r0 = blockIdx.x * 256;
    int rend = min(r0 + 256, NN);
    float s = 0.f, q = 0.f;
    for (int r = r0 + rlocal; r < rend; r += rstride) {
        float v = X[(size_t)r * C + c];
        s += v; q += v * v;
    }
    atomicAdd(&g_bnstats[c], s);
    atomicAdd(&g_bnstats[256 + c], q);
}

__global__ void bn_params_k(const float* __restrict__ g, const float* __restrict__ beta, int C) {
    int c = threadIdx.x;
    if (c < C) {
        float mu = g_bnstats[c] / (float)NN;
        float var = g_bnstats[256 + c] / (float)NN - mu * mu;
        float sc = rsqrtf(var + 1e-5f) * g[c];
        g_scale[c] = sc;
        g_shift[c] = beta[c] - mu * sc;
    }
}

// ---------------- GCN ----------------
__global__ void dinv_k() {
    int i = blockIdx.x * blockDim.x + threadIdx.x;
    if (i >= NN) return;
    float d = (float)(g_rowptr[i + 1] - g_rowptr[i]);
    g_dinv[i] = rsqrtf(fmaxf(d, 1e-12f));
}

__global__ void gcn_agg_k(const float* __restrict__ bg) {
    int warp = (blockIdx.x * blockDim.x + threadIdx.x) >> 5;
    int lane = threadIdx.x & 31;
    if (warp >= NN) return;
    int n = warp;
    float dn = g_dinv[n];
    float2 acc = make_float2(0.f, 0.f);
    const float2* base = (const float2*)g_hp;
    int jb = g_rowptr[n], je = g_rowptr[n + 1];
    for (int j = jb; j < je; j++) {
        int s = __ldg(g_srcs + j);
        float w = g_dinv[s] * dn;
        float2 v = base[(size_t)s * 32 + lane];
        acc.x = fmaf(w, v.x, acc.x);
        acc.y = fmaf(w, v.y, acc.y);
    }
    float2 o;
    o.x = acc.x + bg[lane * 2];
    o.y = acc.y + bg[lane * 2 + 1];
    *(float2*)(g_hgcn + (size_t)n * 64 + lane * 2) = o;
}

// ---------------- GAT2 (single head) ----------------
__global__ void dots2_k(const float* __restrict__ asrc, const float* __restrict__ adst) {
    int warp = (blockIdx.x * blockDim.x + threadIdx.x) >> 5;
    int lane = threadIdx.x & 31;
    if (warp >= NN) return;
    const float* row = g_h3 + (size_t)warp * 64;
    float v0 = row[lane], v1 = row[lane + 32];
    float ps = v0 * asrc[lane] + v1 * asrc[lane + 32];
    float pd = v0 * adst[lane] + v1 * adst[lane + 32];
    #pragma unroll
    for (int o = 16; o; o >>= 1) {
        ps += __shfl_xor_sync(0xffffffffu, ps, o);
        pd += __shfl_xor_sync(0xffffffffu, pd, o);
    }
    if (lane == 0) { g_es2[warp] = ps; g_ed2[warp] = pd; }
}

__global__ void gat2_agg_k(const float* __restrict__ b2) {
    int warp = (blockIdx.x * blockDim.x + threadIdx.x) >> 5;
    int lane = threadIdx.x & 31;
    if (warp >= NN) return;
    int n = warp;
    int jb = g_rowptr[n], je = g_rowptr[n + 1];
    float edv = g_ed2[n];

    // pass 1: max, lane-parallel
    float m = -1e30f;
    for (int j = jb + lane; j < je; j += 32) {
        int s = __ldg(g_srcs + j);
        float e = g_es2[s] + edv;
        e = fmaxf(e, 0.2f * e);
        m = fmaxf(m, e);
    }
    #pragma unroll
    for (int o = 16; o; o >>= 1)
        m = fmaxf(m, __shfl_xor_sync(0xffffffffu, m, o));

    // pass 2
    float den = 0.f;
    float2 acc = make_float2(0.f, 0.f);
    const float2* base = (const float2*)g_h3;
    for (int j = jb; j < je; j++) {
        int s = __ldg(g_srcs + j);
        float e = g_es2[s] + edv;
        e = fmaxf(e, 0.2f * e);
        float w = __expf(e - m);
        den += w;
        float2 v = base[(size_t)s * 32 + lane];
        acc.x = fmaf(w, v.x, acc.x);
        acc.y = fmaf(w, v.y, acc.y);
    }
    float inv = 1.f / (den + 1e-16f);
    float2 o;
    o.x = acc.x * inv + b2[lane * 2];
    o.y = acc.y * inv + b2[lane * 2 + 1];
    *(float2*)(g_hga2 + (size_t)n * 64 + lane * 2) = o;
}

// ---------------- host ----------------
static float* symf(const void* sym) {
    void* p = nullptr;
    cudaGetSymbolAddress(&p, sym);
    return (float*)p;
}

extern "C" void kernel_launch(void* const* d_in, const int* in_sizes, int n_in,
                              void* d_out, int out_size) {
    const float* x   = (const float*)d_in[0];
    const int*   ei  = (const int*)d_in[1];
    // d_in[2] = edge_attr (ignored by reference)
    const float* W1  = (const float*)d_in[3];
    const float* as1 = (const float*)d_in[4];
    const float* ad1 = (const float*)d_in[5];
    const float* b1  = (const float*)d_in[6];
    const float* g1  = (const float*)d_in[7];
    const float* be1 = (const float*)d_in[8];
    const float* Wg  = (const float*)d_in[9];
    const float* bg  = (const float*)d_in[10];
    const float* g2  = (const float*)d_in[11];
    const float* be2 = (const float*)d_in[12];
    const float* W2  = (const float*)d_in[13];
    const float* as2 = (const float*)d_in[14];
    const float* ad2 = (const float*)d_in[15];
    const float* b2  = (const float*)d_in[16];
    const float* g3  = (const float*)d_in[17];
    const float* be3 = (const float*)d_in[18];
    const float* Wp1 = (const float*)d_in[19];
    const float* bp1 = (const float*)d_in[20];
    const float* Wp2 = (const float*)d_in[21];
    const float* bp2 = (const float*)d_in[22];
    float* out = (float*)d_out;

    float* p_h1   = symf(g_h1);
    float* p_hga  = symf(g_hga);
    float* p_hp   = symf(g_hp);
    float* p_hgcn = symf(g_hgcn);
    float* p_h3   = symf(g_h3);
    float* p_hga2 = symf(g_hga2);
    float* p_p1   = symf(g_p1);
    float* p_sc   = symf(g_scale);
    float* p_sh   = symf(g_shift);

    const int EB = (ET + 255) / 256;            // edge-parallel grid
    const int WB = (NN + 7) / 8;                // warp-per-node grid (8 warps/block)
    const int GX = (NN + 127) / 128;            // sgemm2 row blocks (391)

    zdeg_k<<<(NN + 255) / 256, 256>>>();

    // h1 = x @ W1
    sgemm2<<<dim3(GX, 4), 256>>>(x, W1, p_h1, NN, 128, 256, nullptr, 0, nullptr, nullptr, 0);
    dots1_k<<<WB, 256>>>(as1, ad1);

    // CSR by dst (with self loops)
    hist_k<<<EB, 256>>>(ei);
    scan_k<<<1, 1024>>>();
    scatter_k<<<EB, 256>>>(ei);

    // GAT layer 1 (fused softmax)
    gat1_agg_k<<<WB, 256>>>(b1);

    // BN1 params (ELU fused into next GEMM's A path)
    zstats_k<<<1, 512>>>();
    bn_stats_k<<<(NN + 255) / 256, 256>>>(p_hga, 256);
    bn_params_k<<<1, 256>>>(g1, be1, 256);

    // GCN: hp = (BN1+ELU)(hga) @ Wg
    sgemm2<<<dim3(GX, 1), 256>>>(p_hga, Wg, p_hp, NN, 256, 64, nullptr, 0, p_sc, p_sh, 2);
    dinv_k<<<(NN + 255) / 256, 256>>>();
    gcn_agg_k<<<WB, 256>>>(bg);

    // BN2 params (ReLU fused into next GEMM's A path)
    zstats_k<<<1, 512>>>();
    bn_stats_k<<<(NN + 255) / 256, 256>>>(p_hgcn, 64);
    bn_params_k<<<1, 256>>>(g2, be2, 64);

    // GAT layer 2: h3 = (BN2+ReLU)(hgcn) @ W2
    sgemm2<<<dim3(GX, 1), 256>>>(p_hgcn, W2, p_h3, NN, 64, 64, nullptr, 0, p_sc, p_sh, 1);
    dots2_k<<<WB, 256>>>(as2, ad2);
    gat2_agg_k<<<WB, 256>>>(b2);

    // BN3 params (ELU fused into next GEMM's A path)
    zstats_k<<<1, 512>>>();
    bn_stats_k<<<(NN + 255) / 256, 256>>>(p_hga2, 64);
    bn_params_k<<<1, 256>>>(g3, be3, 64);

    // projector: p1 = relu((BN3+ELU)(hga2) @ Wp1 + bp1); out = p1 @ Wp2 + bp2
    sgemm2<<<dim3(GX, 2), 256>>>(p_hga2, Wp1, p_p1, NN, 64, 128, bp1, 1, p_sc, p_sh, 2);
    sgemm2<<<dim3(GX, 1), 256>>>(p_p1, Wp2, out, NN, 128, 64, bp2, 0, nullptr, nullptr, 0);
}